// round 15
// baseline (speedup 1.0000x reference)
#include <cuda_runtime.h>
#include <cuda_bf16.h>
#include <math.h>
#include <stdint.h>

// Problem constants
#define SS   512
#define BB   32
#define DD   1024
#define HH   1024
#define G4H  4096          // 4*H
#define BH   (BB*HH)       // 32768
#define GRID 128

typedef unsigned long long ull;

// ldmatrix x4 (non-transposed, b16)
#define LDSM_X4(r0, r1, r2, r3, addr) \
    asm volatile("ldmatrix.sync.aligned.m8n8.x4.shared.b16 {%0,%1,%2,%3}, [%4];" \
                 : "=r"(r0), "=r"(r1), "=r"(r2), "=r"(r3) : "r"(addr))

// HMMA m16n8k16 bf16 -> f32
#define MMA16816(d, a, b) \
    asm volatile("mma.sync.aligned.m16n8k16.row.col.f32.bf16.bf16.f32 " \
                 "{%0,%1,%2,%3}, {%4,%5,%6,%7}, {%8,%9}, {%0,%1,%2,%3};" \
                 : "+f"((d)[0]), "+f"((d)[1]), "+f"((d)[2]), "+f"((d)[3]) \
                 : "r"((a)[0]), "r"((a)[1]), "r"((a)[2]), "r"((a)[3]), \
                   "r"((b)[0]), "r"((b)[1]))

// cp.async 16B
#define CP_ASYNC16(dst, src) \
    asm volatile("cp.async.cg.shared.global [%0], [%1], 16;" \
                 :: "r"(dst), "l"(src))
#define CP_COMMIT() asm volatile("cp.async.commit_group;")
#define CP_WAIT(n)  asm volatile("cp.async.wait_group %0;" :: "n"(n))

// ---------------- scratch ---------------------------------------------------
__device__ float g_X[(size_t)SS * BB * G4H];             // 256 MB
__device__ __nv_bfloat16 g_Ahi[(size_t)SS * BB * DD];
__device__ __nv_bfloat16 g_Alo[(size_t)SS * BB * DD];
__device__ __nv_bfloat16 g_Uhi[(size_t)G4H * DD];
__device__ __nv_bfloat16 g_Ulo[(size_t)G4H * DD];
__device__ __nv_bfloat16 g_Vhi[(size_t)G4H * HH];
__device__ __nv_bfloat16 g_Vlo[(size_t)G4H * HH];
__device__ __nv_bfloat16 g_hhi[BH];                      // live h state, bf16 hi
__device__ __nv_bfloat16 g_hlo[BH];                      // live h state, bf16 lo

// ---------------- global barrier state (returns to 0 after every run) ------
__device__ unsigned g_bar_ctr = 0;
__device__ volatile unsigned g_bar_flag = 0;

__device__ __forceinline__ uint32_t smem_u32(const void* p) {
    uint32_t a;
    asm("{ .reg .u64 t; cvta.to.shared.u64 t, %1; cvt.u32.u64 %0, t; }"
        : "=r"(a) : "l"(p));
    return a;
}

// ============================================================================
// Split fp32 -> bf16 (hi, lo):  x = hi + lo + O(2^-18 x)
// ============================================================================
__global__ void __launch_bounds__(256) split_bf16(
    const float* __restrict__ src,
    __nv_bfloat16* __restrict__ hi,
    __nv_bfloat16* __restrict__ lo,
    int n4)
{
    int i = blockIdx.x * 256 + threadIdx.x;
    if (i >= n4) return;
    float4 v = ((const float4*)src)[i];
    float vv[4] = {v.x, v.y, v.z, v.w};
    unsigned short hs[4], ls[4];
    #pragma unroll
    for (int j = 0; j < 4; j++) {
        __nv_bfloat16 h = __float2bfloat16(vv[j]);
        __nv_bfloat16 l = __float2bfloat16(vv[j] - __bfloat162float(h));
        hs[j] = *reinterpret_cast<unsigned short*>(&h);
        ls[j] = *reinterpret_cast<unsigned short*>(&l);
    }
    uint2 ph, pl;
    ph.x = (uint32_t)hs[0] | ((uint32_t)hs[1] << 16);
    ph.y = (uint32_t)hs[2] | ((uint32_t)hs[3] << 16);
    pl.x = (uint32_t)ls[0] | ((uint32_t)ls[1] << 16);
    pl.y = (uint32_t)ls[2] | ((uint32_t)ls[3] << 16);
    ((uint2*)hi)[i] = ph;
    ((uint2*)lo)[i] = pl;
}

// ============================================================================
// Kernel A: HMMA GEMM  X = A @ U^T + bias — 3-stage cp.async ring,
//   single __syncthreads per k-chunk. Same math/fragments as R9-R14.
// ============================================================================
#define RPAD 40                       // halves per smem row (32 data + 8 pad)
#define GSTAGE 40960                  // 4 tiles * 128 rows * 80 B
#define GOFF_BIAS (3 * GSTAGE)        // 122880
#define GEMM_SMEM (GOFF_BIAS + 512)   // 123392

__global__ void __launch_bounds__(256) gemm_x_hmma(
    const __nv_bfloat16* __restrict__ Ahi, const __nv_bfloat16* __restrict__ Alo,
    const __nv_bfloat16* __restrict__ Bhi, const __nv_bfloat16* __restrict__ Blo,
    const float* __restrict__ bih, const float* __restrict__ bhh,
    float* __restrict__ X)
{
    extern __shared__ char gsm[];
    float* bias_s = (float*)(gsm + GOFF_BIAS);
    const uint32_t sb = smem_u32(gsm);

    const int tid  = threadIdx.x;
    const int lane = tid & 31;
    const int wid  = tid >> 5;
    const int wm   = (wid >> 1) * 32;
    const int wn   = (wid & 1) * 64;

    const int bn = blockIdx.x * 128;
    const int bm = blockIdx.y * 128;

    if (tid < 128) bias_s[tid] = bih[bn + tid] + bhh[bn + tid];

    const int seg0 = tid * 2;
    const int row0s = seg0 >> 2, sk0 = (seg0 & 3) * 8;
    const int row1s = (seg0 + 1) >> 2, sk1 = ((seg0 + 1) & 3) * 8;

    const __nv_bfloat16* gsrc[4] = {
        Ahi + (size_t)bm * DD, Alo + (size_t)bm * DD,
        Bhi + (size_t)bn * DD, Blo + (size_t)bn * DD };
    const int toff[4] = { 0, 10240, 20480, 30720 };

    // per-thread byte offsets within a stage tile
    const uint32_t d0 = (uint32_t)row0s * 80 + (uint32_t)sk0 * 2;
    const uint32_t d1 = (uint32_t)row1s * 80 + (uint32_t)sk1 * 2;

    const uint32_t aoff = (uint32_t)(lane & 15) * 80 + (uint32_t)(lane >> 4) * 16;
    const uint32_t boff = ((uint32_t)((lane & 7) + (lane >> 4) * 8)) * 80
                        + (uint32_t)((lane >> 3) & 1) * 16;

    float acc[2][8][4];
    #pragma unroll
    for (int im = 0; im < 2; im++)
        #pragma unroll
        for (int ia = 0; ia < 8; ia++)
            #pragma unroll
            for (int q = 0; q < 4; q++) acc[im][ia][q] = 0.f;

    // prologue: stage chunks 0 and 1
    #pragma unroll
    for (int p = 0; p < 2; p++) {
        const uint32_t st = sb + (uint32_t)p * GSTAGE;
        #pragma unroll
        for (int t = 0; t < 4; t++) {
            CP_ASYNC16(st + toff[t] + d0, gsrc[t] + (size_t)row0s * DD + p * 32 + sk0);
            CP_ASYNC16(st + toff[t] + d1, gsrc[t] + (size_t)row1s * DD + p * 32 + sk1);
        }
        CP_COMMIT();
    }

    for (int kc = 0; kc < 32; kc++) {
        if (kc < 31) { CP_WAIT(1); } else { CP_WAIT(0); }
        __syncthreads();   // buf[kc%3] ready to read; buf[(kc+2)%3] free to fill

        if (kc + 2 < 32) {
            const uint32_t st = sb + (uint32_t)((kc + 2) % 3) * GSTAGE;
            #pragma unroll
            for (int t = 0; t < 4; t++) {
                CP_ASYNC16(st + toff[t] + d0,
                           gsrc[t] + (size_t)row0s * DD + (kc + 2) * 32 + sk0);
                CP_ASYNC16(st + toff[t] + d1,
                           gsrc[t] + (size_t)row1s * DD + (kc + 2) * 32 + sk1);
            }
            CP_COMMIT();
        }

        const uint32_t st = sb + (uint32_t)(kc % 3) * GSTAGE;
        #pragma unroll
        for (int ks2 = 0; ks2 < 2; ks2++) {
            const uint32_t kb = ks2 * 32;

            uint32_t ah[2][4], al[2][4];
            #pragma unroll
            for (int im = 0; im < 2; im++) {
                const uint32_t ro = (uint32_t)(wm + im * 16) * 80 + kb;
                LDSM_X4(ah[im][0], ah[im][1], ah[im][2], ah[im][3],
                        st + 0     + ro + aoff);
                LDSM_X4(al[im][0], al[im][1], al[im][2], al[im][3],
                        st + 10240 + ro + aoff);
            }
            uint32_t bh[4][4], bl[4][4];
            #pragma unroll
            for (int g = 0; g < 4; g++) {
                const uint32_t ro = (uint32_t)(wn + g * 16) * 80 + kb;
                LDSM_X4(bh[g][0], bh[g][1], bh[g][2], bh[g][3],
                        st + 20480 + ro + boff);
                LDSM_X4(bl[g][0], bl[g][1], bl[g][2], bl[g][3],
                        st + 30720 + ro + boff);
            }

            #pragma unroll
            for (int im = 0; im < 2; im++)
                #pragma unroll
                for (int g = 0; g < 4; g++)
                    #pragma unroll
                    for (int h = 0; h < 2; h++) {
                        const int ia = 2 * g + h;
                        uint32_t bhf[2] = { bh[g][h * 2], bh[g][h * 2 + 1] };
                        uint32_t blf[2] = { bl[g][h * 2], bl[g][h * 2 + 1] };
                        MMA16816(acc[im][ia], ah[im], bhf);
                        MMA16816(acc[im][ia], ah[im], blf);
                        MMA16816(acc[im][ia], al[im], bhf);
                    }
        }
    }

    const int trow = lane >> 2;
    const int tcol = (lane & 3) * 2;
    #pragma unroll
    for (int im = 0; im < 2; im++) {
        #pragma unroll
        for (int ia = 0; ia < 8; ia++) {
            const int nloc = wn + ia * 8 + tcol;
            const float b0 = bias_s[nloc], b1 = bias_s[nloc + 1];
            const size_t r0 = (size_t)(bm + wm + im * 16 + trow) * G4H + bn + nloc;
            const size_t r1 = r0 + (size_t)8 * G4H;
            float2 o0 = { acc[im][ia][0] + b0, acc[im][ia][1] + b1 };
            float2 o1 = { acc[im][ia][2] + b0, acc[im][ia][3] + b1 };
            *(float2*)&X[r0] = o0;
            *(float2*)&X[r1] = o1;
        }
    }
}

// ============================================================================
// Kernel B: PERSISTENT LSTM — R14 structure; staging LDGs issued FIRST each
//   step (deferred stores drain in their shadow).
// ============================================================================
#define PTHREADS  512
#define HROWB     2064                 // bytes per h smem row (2048 + 16 pad)
#define OFF_HHI   0
#define OFF_HLO   (32 * HROWB)                 // 66048
#define OFF_PB    (2 * 32 * HROWB)             // 132096
#define OFF_XG    (OFF_PB + 8 * 32 * 34 * 4)   // +34816 = 166912
#define PERS_SMEM (OFF_XG + 4 * 32 * 8 * 4)    // +4096 = 171008

__device__ __forceinline__ float fsig(float x) {
    return __fdividef(1.f, 1.f + __expf(-x));
}
__device__ __forceinline__ float ftanh(float x) {
    float e = __expf(-2.f * x);
    return __fdividef(1.f - e, 1.f + e);
}

__global__ void __launch_bounds__(PTHREADS, 1) lstm_persistent(
    const float* __restrict__ X,
    const float* __restrict__ c0,
    const __nv_bfloat16* __restrict__ Vhi,
    const __nv_bfloat16* __restrict__ Vlo,
    __nv_bfloat16* __restrict__ hhi,
    __nv_bfloat16* __restrict__ hlo,
    float* __restrict__ all_h1,
    float* __restrict__ all_h2,
    float* __restrict__ all_c,
    float* __restrict__ h_f,
    float* __restrict__ c_f)
{
    extern __shared__ char smx[];
    float* pb   = (float*)(smx + OFF_PB);    // [8 wk][32 rows][34 b]
    float* xg_s = (float*)(smx + OFF_XG);    // [4 g][32 b][8 c]

    const int tid  = threadIdx.x;
    const int cb   = blockIdx.x;
    const int lane = tid & 31;
    const int w    = tid >> 5;       // warp 0..15
    const int wm   = w & 1;          // m-half: rows [16wm, 16wm+16); also hi/lo stager
    const int wk   = w >> 1;         // k-slice: [wk*128, wk*128+128)

    // ---- combine/cell mapping (threads 0..255) ----
    const int cbb = tid >> 3;        // batch
    const int ccc = tid & 7;         // column
    const int ooff = cbb * HH + cb * 8 + ccc;

    // ---- V fragments in registers: A-frag m16k16, 8 ksteps, hi+lo ----
    uint32_t vhi[8][4], vlo[8][4];
    {
        const int lr0 = 16 * wm + (lane >> 2);
        const int lr1 = lr0 + 8;
        const size_t gr0 = (size_t)(lr0 >> 3) * HH + cb * 8 + (lr0 & 7);
        const size_t gr1 = (size_t)(lr1 >> 3) * HH + cb * 8 + (lr1 & 7);
        const int kb0 = wk * 128 + (lane & 3) * 2;
        #pragma unroll
        for (int ks = 0; ks < 8; ks++) {
            const int k = kb0 + ks * 16;
            vhi[ks][0] = *(const uint32_t*)(Vhi + gr0 * HH + k);
            vhi[ks][1] = *(const uint32_t*)(Vhi + gr1 * HH + k);
            vhi[ks][2] = *(const uint32_t*)(Vhi + gr0 * HH + k + 8);
            vhi[ks][3] = *(const uint32_t*)(Vhi + gr1 * HH + k + 8);
            vlo[ks][0] = *(const uint32_t*)(Vlo + gr0 * HH + k);
            vlo[ks][1] = *(const uint32_t*)(Vlo + gr1 * HH + k);
            vlo[ks][2] = *(const uint32_t*)(Vlo + gr0 * HH + k + 8);
            vlo[ks][3] = *(const uint32_t*)(Vlo + gr1 * HH + k + 8);
        }
    }

    float c_reg = (tid < 256) ? c0[ooff] : 0.f;
    float hn_prev = 0.f, cn_prev = 0.f;

    // ldmatrix B addresses (h): row = batch, cols = k (non-transposed)
    const uint32_t sb = smem_u32(smx);
    const uint32_t lm_row = (lane & 7) + ((lane >> 4) & 1) * 8;
    const uint32_t lm_k16 = ((lane >> 3) & 1) * 16;
    const uint32_t bhi_g0 = sb + OFF_HHI + lm_row * HROWB + lm_k16 + wk * 256;
    const uint32_t bhi_g1 = bhi_g0 + 16 * HROWB;
    const uint32_t blo_g0 = bhi_g0 + OFF_HLO;
    const uint32_t blo_g1 = bhi_g1 + OFF_HLO;

    // per-pair staging pointers (wm==0 stages hi, wm==1 stages lo)
    const uint4* hsrc = (wm == 0) ? (const uint4*)hhi : (const uint4*)hlo;
    char* hdst = smx + (wm == 0 ? OFF_HHI : OFF_HLO);

    // Xg mapping (tid<256)
    const int xg_g = tid & 3, xg_half = (tid >> 2) & 1, xg_b = tid >> 3;
    const float* xsrc = X + (size_t)xg_b * G4H + (size_t)xg_g * HH
                          + cb * 8 + xg_half * 4;

    // prefetch Xg for s=0
    float4 xv;
    if (tid < 256) xv = *(const float4*)(xsrc);

    for (int s = 0; s < SS; s++) {
        // ---- h staging LDGs FIRST (critical path to named bar -> MMA) ----
        uint4 hv[16];
        #pragma unroll
        for (int it = 0; it < 16; it++) {
            const int b = it * 2 + (lane >> 4);
            const int q = lane & 15;
            hv[it] = hsrc[b * 128 + wk * 16 + q];
        }

        // ---- deferred output stores from previous step (in LDG shadow) ----
        if (s > 0 && tid < 256) {
            const size_t po = (size_t)(s - 1) * BH + ooff;
            all_h1[po] = hn_prev;
            all_h2[po] = hn_prev;
            all_c [po] = cn_prev;
        }

        // ---- write staged h into smem + Xg tile ----
        #pragma unroll
        for (int it = 0; it < 16; it++) {
            const int b = it * 2 + (lane >> 4);
            const int q = lane & 15;
            *(uint4*)(hdst + b * HROWB + (wk * 16 + q) * 16) = hv[it];
        }
        if (tid < 256)
            *(float4*)&xg_s[(xg_g * 32 + xg_b) * 8 + xg_half * 4] = xv;
        asm volatile("bar.sync %0, 64;" :: "r"(wk + 1) : "memory");

        // ---- HMMA: 8 ksteps x (4 LDSM.x4 + 12 MMA) ----
        float acc[4][4];
        #pragma unroll
        for (int nt = 0; nt < 4; nt++)
            #pragma unroll
            for (int q = 0; q < 4; q++) acc[nt][q] = 0.f;

        #pragma unroll
        for (int ks = 0; ks < 8; ks++) {
            const uint32_t kb = ks * 32;
            uint32_t h0[4], h1[4], l0[4], l1[4];
            LDSM_X4(h0[0], h0[1], h0[2], h0[3], bhi_g0 + kb);
            LDSM_X4(h1[0], h1[1], h1[2], h1[3], bhi_g1 + kb);
            LDSM_X4(l0[0], l0[1], l0[2], l0[3], blo_g0 + kb);
            LDSM_X4(l1[0], l1[1], l1[2], l1[3], blo_g1 + kb);
            MMA16816(acc[0], vhi[ks], &h0[0]);
            MMA16816(acc[0], vhi[ks], &l0[0]);
            MMA16816(acc[0], vlo[ks], &h0[0]);
            MMA16816(acc[1], vhi[ks], &h0[2]);
            MMA16816(acc[1], vhi[ks], &l0[2]);
            MMA16816(acc[1], vlo[ks], &h0[2]);
            MMA16816(acc[2], vhi[ks], &h1[0]);
            MMA16816(acc[2], vhi[ks], &l1[0]);
            MMA16816(acc[2], vlo[ks], &h1[0]);
            MMA16816(acc[3], vhi[ks], &h1[2]);
            MMA16816(acc[3], vhi[ks], &l1[2]);
            MMA16816(acc[3], vlo[ks], &h1[2]);
        }

        // ---- partials -> pb[wk][row][34] ----
        {
            const int prow = 16 * wm + (lane >> 2);
            const int pcol = (lane & 3) * 2;
            float* pw0 = pb + (wk * 32 + prow) * 34;
            float* pw1 = pw0 + 8 * 34;
            #pragma unroll
            for (int nt = 0; nt < 4; nt++) {
                float2 u = { acc[nt][0], acc[nt][1] };
                float2 v = { acc[nt][2], acc[nt][3] };
                *(float2*)&pw0[nt * 8 + pcol] = u;
                *(float2*)&pw1[nt * 8 + pcol] = v;
            }
        }
        __syncthreads();

        // ---- combine + cell (threads 0..255) ----
        if (tid < 256) {
            float g4[4];
            #pragma unroll
            for (int g = 0; g < 4; g++) {
                const int lrr = g * 8 + ccc;
                float acm = xg_s[(g * 32 + cbb) * 8 + ccc];
                #pragma unroll
                for (int k2 = 0; k2 < 8; k2++)
                    acm += pb[(k2 * 32 + lrr) * 34 + cbb];
                g4[g] = acm;
            }

            const float iv = fsig(g4[0]);
            const float fv = fsig(g4[1]);
            const float gg = ftanh(g4[2]);
            const float ov = fsig(g4[3]);

            c_reg = fv * c_reg + iv * gg;
            const float hn = ov * ftanh(c_reg);
            hn_prev = hn;
            cn_prev = c_reg;

            __nv_bfloat16 hh = __float2bfloat16(hn);
            __nv_bfloat16 hl = __float2bfloat16(hn - __bfloat162float(hh));
            hhi[ooff] = hh;
            hlo[ooff] = hl;

            // prefetch Xg for next step (latency hides in the barrier)
            if (s + 1 < SS)
                xv = *(const float4*)(xsrc + (size_t)(s + 1) * BB * G4H);
        }

        // ---- grid barrier (writer-only fence; R11-proven tid0 spin) ----
        if (tid < 256) __threadfence();
        __syncthreads();
        if (tid == 0) {
            const unsigned target = (s & 1) ? 0u : 1u;
            unsigned old = atomicAdd(&g_bar_ctr, 1u);
            if (old == GRID - 1) {
                atomicExch(&g_bar_ctr, 0u);
                __threadfence();
                g_bar_flag = target;
            } else {
                while (g_bar_flag != target) { }
            }
            __threadfence();
        }
        __syncthreads();
    }

    // ---- final deferred stores + final state ----
    if (tid < 256) {
        const size_t po = (size_t)(SS - 1) * BH + ooff;
        all_h1[po] = hn_prev;
        all_h2[po] = hn_prev;
        all_c [po] = cn_prev;
        h_f[ooff] = hn_prev;
        c_f[ooff] = cn_prev;
    }
}

// ============================================================================
// Launch
// ============================================================================
extern "C" void kernel_launch(void* const* d_in, const int* in_sizes, int n_in,
                              void* d_out, int out_size)
{
    const float* layer_input = (const float*)d_in[0];  // [S,B,D]
    const float* h_t         = (const float*)d_in[1];  // [B,H]
    const float* c_t         = (const float*)d_in[2];  // [B,H]
    const float* U           = (const float*)d_in[3];  // [4H,D]
    const float* V           = (const float*)d_in[4];  // [4H,H]
    const float* bih         = (const float*)d_in[5];  // [4H]
    const float* bhh         = (const float*)d_in[6];  // [4H]

    float* out = (float*)d_out;
    float* all_h1 = out;
    float* h_f    = out + (size_t)SS * BH;
    float* c_f    = h_f + BH;
    float* all_h2 = c_f + BH;
    float* all_c  = all_h2 + (size_t)SS * BH;

    float* Xp = nullptr;
    cudaGetSymbolAddress((void**)&Xp, g_X);
    __nv_bfloat16 *Ahi, *Alo, *Uhi, *Ulo, *Vhi, *Vlo, *hhi, *hlo;
    cudaGetSymbolAddress((void**)&Ahi, g_Ahi);
    cudaGetSymbolAddress((void**)&Alo, g_Alo);
    cudaGetSymbolAddress((void**)&Uhi, g_Uhi);
    cudaGetSymbolAddress((void**)&Ulo, g_Ulo);
    cudaGetSymbolAddress((void**)&Vhi, g_Vhi);
    cudaGetSymbolAddress((void**)&Vlo, g_Vlo);
    cudaGetSymbolAddress((void**)&hhi, g_hhi);
    cudaGetSymbolAddress((void**)&hlo, g_hlo);

    cudaFuncSetAttribute(lstm_persistent,
                         cudaFuncAttributeMaxDynamicSharedMemorySize, PERS_SMEM);
    cudaFuncSetAttribute(gemm_x_hmma,
                         cudaFuncAttributeMaxDynamicSharedMemorySize, GEMM_SMEM);

    // 0) bf16 hi/lo splits: A, U, V, h0
    const int nA4 = SS * BB * DD / 4;
    const int nU4 = G4H * DD / 4;
    const int nV4 = G4H * HH / 4;
    const int nH4 = BH / 4;
    split_bf16<<<nA4 / 256, 256>>>(layer_input, Ahi, Alo, nA4);
    split_bf16<<<nU4 / 256, 256>>>(U, Uhi, Ulo, nU4);
    split_bf16<<<nV4 / 256, 256>>>(V, Vhi, Vlo, nV4);
    split_bf16<<<nH4 / 256, 256>>>(h_t, hhi, hlo, nH4);

    // 1) HMMA input projection + bias (3-stage cp.async pipeline)
    dim3 gg(G4H / 128, (SS * BB) / 128);   // (32, 128)
    gemm_x_hmma<<<gg, 256, GEMM_SMEM>>>(Ahi, Alo, Uhi, Ulo, bih, bhh, Xp);

    // 2) persistent HMMA recurrence (all 512 steps)
    lstm_persistent<<<GRID, PTHREADS, PERS_SMEM>>>(
        Xp, c_t, Vhi, Vlo, hhi, hlo,
        all_h1, all_h2, all_c, h_f, c_f);
}

// round 16
// speedup vs baseline: 1.2046x; 1.2046x over previous
#include <cuda_runtime.h>
#include <cuda_bf16.h>
#include <math.h>
#include <stdint.h>

// Problem constants
#define SS   512
#define BB   32
#define DD   1024
#define HH   1024
#define G4H  4096          // 4*H
#define BH   (BB*HH)       // 32768
#define GRID 128

typedef unsigned long long ull;

// ldmatrix x4 (non-transposed, b16)
#define LDSM_X4(r0, r1, r2, r3, addr) \
    asm volatile("ldmatrix.sync.aligned.m8n8.x4.shared.b16 {%0,%1,%2,%3}, [%4];" \
                 : "=r"(r0), "=r"(r1), "=r"(r2), "=r"(r3) : "r"(addr))

// HMMA m16n8k16 bf16 -> f32
#define MMA16816(d, a, b) \
    asm volatile("mma.sync.aligned.m16n8k16.row.col.f32.bf16.bf16.f32 " \
                 "{%0,%1,%2,%3}, {%4,%5,%6,%7}, {%8,%9}, {%0,%1,%2,%3};" \
                 : "+f"((d)[0]), "+f"((d)[1]), "+f"((d)[2]), "+f"((d)[3]) \
                 : "r"((a)[0]), "r"((a)[1]), "r"((a)[2]), "r"((a)[3]), \
                   "r"((b)[0]), "r"((b)[1]))

// cp.async 16B
#define CP_ASYNC16(dst, src) \
    asm volatile("cp.async.cg.shared.global [%0], [%1], 16;" \
                 :: "r"(dst), "l"(src))
#define CP_COMMIT() asm volatile("cp.async.commit_group;")
#define CP_WAIT(n)  asm volatile("cp.async.wait_group %0;" :: "n"(n))

// ---------------- scratch ---------------------------------------------------
__device__ float g_X[(size_t)SS * BB * G4H];             // 256 MB
__device__ __nv_bfloat16 g_Ahi[(size_t)SS * BB * DD];
__device__ __nv_bfloat16 g_Alo[(size_t)SS * BB * DD];
__device__ __nv_bfloat16 g_Uhi[(size_t)G4H * DD];
__device__ __nv_bfloat16 g_Ulo[(size_t)G4H * DD];
__device__ __nv_bfloat16 g_Vhi[(size_t)G4H * HH];
__device__ __nv_bfloat16 g_Vlo[(size_t)G4H * HH];
__device__ __nv_bfloat16 g_hhi[BH];                      // live h state, bf16 hi
__device__ __nv_bfloat16 g_hlo[BH];                      // live h state, bf16 lo

// ---------------- global barrier state (returns to 0 after every run) ------
__device__ unsigned g_bar_ctr = 0;
__device__ volatile unsigned g_bar_flag = 0;

__device__ __forceinline__ uint32_t smem_u32(const void* p) {
    uint32_t a;
    asm("{ .reg .u64 t; cvta.to.shared.u64 t, %1; cvt.u32.u64 %0, t; }"
        : "=r"(a) : "l"(p));
    return a;
}

// ============================================================================
// Fused split fp32 -> bf16 (hi, lo) for A, U, V, h0 in ONE launch.
//   x = hi + lo + O(2^-18 x). Segment dispatch by flat float4 index.
// ============================================================================
#define N4_A  (SS * BB * DD / 4)          // 4194304
#define N4_U  (G4H * DD / 4)              // 1048576
#define N4_V  (G4H * HH / 4)              // 1048576
#define N4_H  (BH / 4)                    // 8192
#define N4_TOTAL (N4_A + N4_U + N4_V + N4_H)

__global__ void __launch_bounds__(256) split_bf16_all(
    const float* __restrict__ A,  const float* __restrict__ U,
    const float* __restrict__ V,  const float* __restrict__ h0)
{
    int i = blockIdx.x * 256 + threadIdx.x;
    if (i >= N4_TOTAL) return;

    const float* src;
    __nv_bfloat16 *hi, *lo;
    int j = i;
    if (j < N4_A)            { src = A;  hi = g_Ahi; lo = g_Alo; }
    else if ((j -= N4_A) < N4_U) { src = U;  hi = g_Uhi; lo = g_Ulo; }
    else if ((j -= N4_U) < N4_V) { src = V;  hi = g_Vhi; lo = g_Vlo; }
    else     { j -= N4_V;      src = h0; hi = g_hhi; lo = g_hlo; }

    float4 v = ((const float4*)src)[j];
    float vv[4] = {v.x, v.y, v.z, v.w};
    unsigned short hs[4], ls[4];
    #pragma unroll
    for (int q = 0; q < 4; q++) {
        __nv_bfloat16 h = __float2bfloat16(vv[q]);
        __nv_bfloat16 l = __float2bfloat16(vv[q] - __bfloat162float(h));
        hs[q] = *reinterpret_cast<unsigned short*>(&h);
        ls[q] = *reinterpret_cast<unsigned short*>(&l);
    }
    uint2 ph, pl;
    ph.x = (uint32_t)hs[0] | ((uint32_t)hs[1] << 16);
    ph.y = (uint32_t)hs[2] | ((uint32_t)hs[3] << 16);
    pl.x = (uint32_t)ls[0] | ((uint32_t)ls[1] << 16);
    pl.y = (uint32_t)ls[2] | ((uint32_t)ls[3] << 16);
    ((uint2*)hi)[j] = ph;
    ((uint2*)lo)[j] = pl;
}

// ============================================================================
// Kernel A: HMMA GEMM  X = A @ U^T + bias — 2-stage cp.async (R14-proven,
//   82 KB smem -> 2 CTAs/SM; do NOT grow smem past 114 KB).
// ============================================================================
#define RPAD 40                       // halves per smem row (32 data + 8 pad)
#define GSTAGE 40960                  // 4 tiles * 128 rows * 80 B
#define GOFF_BIAS (2 * GSTAGE)        // 81920
#define GEMM_SMEM (GOFF_BIAS + 512)   // 82432  (2 CTAs/SM)

__global__ void __launch_bounds__(256) gemm_x_hmma(
    const __nv_bfloat16* __restrict__ Ahi, const __nv_bfloat16* __restrict__ Alo,
    const __nv_bfloat16* __restrict__ Bhi, const __nv_bfloat16* __restrict__ Blo,
    const float* __restrict__ bih, const float* __restrict__ bhh,
    float* __restrict__ X)
{
    extern __shared__ char gsm[];
    float* bias_s = (float*)(gsm + GOFF_BIAS);
    const uint32_t sb = smem_u32(gsm);

    const int tid  = threadIdx.x;
    const int lane = tid & 31;
    const int wid  = tid >> 5;
    const int wm   = (wid >> 1) * 32;
    const int wn   = (wid & 1) * 64;

    const int bn = blockIdx.x * 128;
    const int bm = blockIdx.y * 128;

    if (tid < 128) bias_s[tid] = bih[bn + tid] + bhh[bn + tid];

    const int seg0 = tid * 2;
    const int row0s = seg0 >> 2, sk0 = (seg0 & 3) * 8;
    const int row1s = (seg0 + 1) >> 2, sk1 = ((seg0 + 1) & 3) * 8;

    const __nv_bfloat16* gsrc[4] = {
        Ahi + (size_t)bm * DD, Alo + (size_t)bm * DD,
        Bhi + (size_t)bn * DD, Blo + (size_t)bn * DD };
    const int toff[4] = { 0, 10240, 20480, 30720 };

    const uint32_t d0 = (uint32_t)row0s * 80 + (uint32_t)sk0 * 2;
    const uint32_t d1 = (uint32_t)row1s * 80 + (uint32_t)sk1 * 2;

    const uint32_t aoff = (uint32_t)(lane & 15) * 80 + (uint32_t)(lane >> 4) * 16;
    const uint32_t boff = ((uint32_t)((lane & 7) + (lane >> 4) * 8)) * 80
                        + (uint32_t)((lane >> 3) & 1) * 16;

    float acc[2][8][4];
    #pragma unroll
    for (int im = 0; im < 2; im++)
        #pragma unroll
        for (int ia = 0; ia < 8; ia++)
            #pragma unroll
            for (int q = 0; q < 4; q++) acc[im][ia][q] = 0.f;

    // prologue: stage chunk 0 into buf0
    {
        const uint32_t st = sb;
        #pragma unroll
        for (int t = 0; t < 4; t++) {
            CP_ASYNC16(st + toff[t] + d0, gsrc[t] + (size_t)row0s * DD + sk0);
            CP_ASYNC16(st + toff[t] + d1, gsrc[t] + (size_t)row1s * DD + sk1);
        }
        CP_COMMIT();
    }

    for (int kc = 0; kc < 32; kc++) {
        if (kc + 1 < 32) {
            const uint32_t st = sb + (uint32_t)((kc + 1) & 1) * GSTAGE;
            #pragma unroll
            for (int t = 0; t < 4; t++) {
                CP_ASYNC16(st + toff[t] + d0,
                           gsrc[t] + (size_t)row0s * DD + (kc + 1) * 32 + sk0);
                CP_ASYNC16(st + toff[t] + d1,
                           gsrc[t] + (size_t)row1s * DD + (kc + 1) * 32 + sk1);
            }
            CP_COMMIT();
            CP_WAIT(1);
        } else {
            CP_WAIT(0);
        }
        __syncthreads();

        const uint32_t st = sb + (uint32_t)(kc & 1) * GSTAGE;
        #pragma unroll
        for (int ks2 = 0; ks2 < 2; ks2++) {
            const uint32_t kb = ks2 * 32;

            uint32_t ah[2][4], al[2][4];
            #pragma unroll
            for (int im = 0; im < 2; im++) {
                const uint32_t ro = (uint32_t)(wm + im * 16) * 80 + kb;
                LDSM_X4(ah[im][0], ah[im][1], ah[im][2], ah[im][3],
                        st + 0     + ro + aoff);
                LDSM_X4(al[im][0], al[im][1], al[im][2], al[im][3],
                        st + 10240 + ro + aoff);
            }
            uint32_t bh[4][4], bl[4][4];
            #pragma unroll
            for (int g = 0; g < 4; g++) {
                const uint32_t ro = (uint32_t)(wn + g * 16) * 80 + kb;
                LDSM_X4(bh[g][0], bh[g][1], bh[g][2], bh[g][3],
                        st + 20480 + ro + boff);
                LDSM_X4(bl[g][0], bl[g][1], bl[g][2], bl[g][3],
                        st + 30720 + ro + boff);
            }

            #pragma unroll
            for (int im = 0; im < 2; im++)
                #pragma unroll
                for (int g = 0; g < 4; g++)
                    #pragma unroll
                    for (int h = 0; h < 2; h++) {
                        const int ia = 2 * g + h;
                        uint32_t bhf[2] = { bh[g][h * 2], bh[g][h * 2 + 1] };
                        uint32_t blf[2] = { bl[g][h * 2], bl[g][h * 2 + 1] };
                        MMA16816(acc[im][ia], ah[im], bhf);
                        MMA16816(acc[im][ia], ah[im], blf);
                        MMA16816(acc[im][ia], al[im], bhf);
                    }
        }
        __syncthreads();   // done reading buf[kc&1] before it is re-staged
    }

    const int trow = lane >> 2;
    const int tcol = (lane & 3) * 2;
    #pragma unroll
    for (int im = 0; im < 2; im++) {
        #pragma unroll
        for (int ia = 0; ia < 8; ia++) {
            const int nloc = wn + ia * 8 + tcol;
            const float b0 = bias_s[nloc], b1 = bias_s[nloc + 1];
            const size_t r0 = (size_t)(bm + wm + im * 16 + trow) * G4H + bn + nloc;
            const size_t r1 = r0 + (size_t)8 * G4H;
            float2 o0 = { acc[im][ia][0] + b0, acc[im][ia][1] + b1 };
            float2 o1 = { acc[im][ia][2] + b0, acc[im][ia][3] + b1 };
            *(float2*)&X[r0] = o0;
            *(float2*)&X[r1] = o1;
        }
    }
}

// ============================================================================
// Kernel B: PERSISTENT LSTM — R14-proven structure (verbatim):
//   per-pair h staging + named barrier, writer-only fence, deferred stores,
//   Xg prefetch across the grid barrier.
// ============================================================================
#define PTHREADS  512
#define HROWB     2064                 // bytes per h smem row (2048 + 16 pad)
#define OFF_HHI   0
#define OFF_HLO   (32 * HROWB)                 // 66048
#define OFF_PB    (2 * 32 * HROWB)             // 132096
#define OFF_XG    (OFF_PB + 8 * 32 * 34 * 4)   // +34816 = 166912
#define PERS_SMEM (OFF_XG + 4 * 32 * 8 * 4)    // +4096 = 171008

__device__ __forceinline__ float fsig(float x) {
    return __fdividef(1.f, 1.f + __expf(-x));
}
__device__ __forceinline__ float ftanh(float x) {
    float e = __expf(-2.f * x);
    return __fdividef(1.f - e, 1.f + e);
}

__global__ void __launch_bounds__(PTHREADS, 1) lstm_persistent(
    const float* __restrict__ X,
    const float* __restrict__ c0,
    const __nv_bfloat16* __restrict__ Vhi,
    const __nv_bfloat16* __restrict__ Vlo,
    __nv_bfloat16* __restrict__ hhi,
    __nv_bfloat16* __restrict__ hlo,
    float* __restrict__ all_h1,
    float* __restrict__ all_h2,
    float* __restrict__ all_c,
    float* __restrict__ h_f,
    float* __restrict__ c_f)
{
    extern __shared__ char smx[];
    float* pb   = (float*)(smx + OFF_PB);    // [8 wk][32 rows][34 b]
    float* xg_s = (float*)(smx + OFF_XG);    // [4 g][32 b][8 c]

    const int tid  = threadIdx.x;
    const int cb   = blockIdx.x;
    const int lane = tid & 31;
    const int w    = tid >> 5;       // warp 0..15
    const int wm   = w & 1;          // m-half: rows [16wm, 16wm+16); also hi/lo stager
    const int wk   = w >> 1;         // k-slice: [wk*128, wk*128+128)

    // ---- combine/cell mapping (threads 0..255) ----
    const int cbb = tid >> 3;        // batch
    const int ccc = tid & 7;         // column
    const int ooff = cbb * HH + cb * 8 + ccc;

    // ---- V fragments in registers: A-frag m16k16, 8 ksteps, hi+lo ----
    uint32_t vhi[8][4], vlo[8][4];
    {
        const int lr0 = 16 * wm + (lane >> 2);
        const int lr1 = lr0 + 8;
        const size_t gr0 = (size_t)(lr0 >> 3) * HH + cb * 8 + (lr0 & 7);
        const size_t gr1 = (size_t)(lr1 >> 3) * HH + cb * 8 + (lr1 & 7);
        const int kb0 = wk * 128 + (lane & 3) * 2;
        #pragma unroll
        for (int ks = 0; ks < 8; ks++) {
            const int k = kb0 + ks * 16;
            vhi[ks][0] = *(const uint32_t*)(Vhi + gr0 * HH + k);
            vhi[ks][1] = *(const uint32_t*)(Vhi + gr1 * HH + k);
            vhi[ks][2] = *(const uint32_t*)(Vhi + gr0 * HH + k + 8);
            vhi[ks][3] = *(const uint32_t*)(Vhi + gr1 * HH + k + 8);
            vlo[ks][0] = *(const uint32_t*)(Vlo + gr0 * HH + k);
            vlo[ks][1] = *(const uint32_t*)(Vlo + gr1 * HH + k);
            vlo[ks][2] = *(const uint32_t*)(Vlo + gr0 * HH + k + 8);
            vlo[ks][3] = *(const uint32_t*)(Vlo + gr1 * HH + k + 8);
        }
    }

    float c_reg = (tid < 256) ? c0[ooff] : 0.f;
    float hn_prev = 0.f, cn_prev = 0.f;

    // ldmatrix B addresses (h): row = batch, cols = k (non-transposed)
    const uint32_t sb = smem_u32(smx);
    const uint32_t lm_row = (lane & 7) + ((lane >> 4) & 1) * 8;
    const uint32_t lm_k16 = ((lane >> 3) & 1) * 16;
    const uint32_t bhi_g0 = sb + OFF_HHI + lm_row * HROWB + lm_k16 + wk * 256;
    const uint32_t bhi_g1 = bhi_g0 + 16 * HROWB;
    const uint32_t blo_g0 = bhi_g0 + OFF_HLO;
    const uint32_t blo_g1 = bhi_g1 + OFF_HLO;

    // per-pair staging pointers (wm==0 stages hi, wm==1 stages lo)
    const uint4* hsrc = (wm == 0) ? (const uint4*)hhi : (const uint4*)hlo;
    char* hdst = smx + (wm == 0 ? OFF_HHI : OFF_HLO);

    // Xg mapping (tid<256)
    const int xg_g = tid & 3, xg_half = (tid >> 2) & 1, xg_b = tid >> 3;
    const float* xsrc = X + (size_t)xg_b * G4H + (size_t)xg_g * HH
                          + cb * 8 + xg_half * 4;

    // prefetch Xg for s=0
    float4 xv;
    if (tid < 256) xv = *(const float4*)(xsrc);

    for (int s = 0; s < SS; s++) {
        // ---- deferred output stores from previous step (post-barrier) ----
        if (s > 0 && tid < 256) {
            const size_t po = (size_t)(s - 1) * BH + ooff;
            all_h1[po] = hn_prev;
            all_h2[po] = hn_prev;
            all_c [po] = cn_prev;
        }

        // ---- per-pair h staging: warp pair (2wk,2wk+1) stages slice wk ----
        #pragma unroll
        for (int it = 0; it < 16; it++) {
            const int b = it * 2 + (lane >> 4);
            const int q = lane & 15;
            uint4 v = hsrc[b * 128 + wk * 16 + q];
            *(uint4*)(hdst + b * HROWB + (wk * 16 + q) * 16) = v;
        }
        if (tid < 256)
            *(float4*)&xg_s[(xg_g * 32 + xg_b) * 8 + xg_half * 4] = xv;
        asm volatile("bar.sync %0, 64;" :: "r"(wk + 1) : "memory");

        // ---- HMMA: 8 ksteps x (4 LDSM.x4 + 12 MMA) ----
        float acc[4][4];
        #pragma unroll
        for (int nt = 0; nt < 4; nt++)
            #pragma unroll
            for (int q = 0; q < 4; q++) acc[nt][q] = 0.f;

        #pragma unroll
        for (int ks = 0; ks < 8; ks++) {
            const uint32_t kb = ks * 32;
            uint32_t h0[4], h1[4], l0[4], l1[4];
            LDSM_X4(h0[0], h0[1], h0[2], h0[3], bhi_g0 + kb);
            LDSM_X4(h1[0], h1[1], h1[2], h1[3], bhi_g1 + kb);
            LDSM_X4(l0[0], l0[1], l0[2], l0[3], blo_g0 + kb);
            LDSM_X4(l1[0], l1[1], l1[2], l1[3], blo_g1 + kb);
            MMA16816(acc[0], vhi[ks], &h0[0]);
            MMA16816(acc[0], vhi[ks], &l0[0]);
            MMA16816(acc[0], vlo[ks], &h0[0]);
            MMA16816(acc[1], vhi[ks], &h0[2]);
            MMA16816(acc[1], vhi[ks], &l0[2]);
            MMA16816(acc[1], vlo[ks], &h0[2]);
            MMA16816(acc[2], vhi[ks], &h1[0]);
            MMA16816(acc[2], vhi[ks], &l1[0]);
            MMA16816(acc[2], vlo[ks], &h1[0]);
            MMA16816(acc[3], vhi[ks], &h1[2]);
            MMA16816(acc[3], vhi[ks], &l1[2]);
            MMA16816(acc[3], vlo[ks], &h1[2]);
        }

        // ---- partials -> pb[wk][row][34] ----
        {
            const int prow = 16 * wm + (lane >> 2);
            const int pcol = (lane & 3) * 2;
            float* pw0 = pb + (wk * 32 + prow) * 34;
            float* pw1 = pw0 + 8 * 34;
            #pragma unroll
            for (int nt = 0; nt < 4; nt++) {
                float2 u = { acc[nt][0], acc[nt][1] };
                float2 v = { acc[nt][2], acc[nt][3] };
                *(float2*)&pw0[nt * 8 + pcol] = u;
                *(float2*)&pw1[nt * 8 + pcol] = v;
            }
        }
        __syncthreads();

        // ---- combine + cell (threads 0..255) ----
        if (tid < 256) {
            float g4[4];
            #pragma unroll
            for (int g = 0; g < 4; g++) {
                const int lrr = g * 8 + ccc;
                float acm = xg_s[(g * 32 + cbb) * 8 + ccc];
                #pragma unroll
                for (int k2 = 0; k2 < 8; k2++)
                    acm += pb[(k2 * 32 + lrr) * 34 + cbb];
                g4[g] = acm;
            }

            const float iv = fsig(g4[0]);
            const float fv = fsig(g4[1]);
            const float gg = ftanh(g4[2]);
            const float ov = fsig(g4[3]);

            c_reg = fv * c_reg + iv * gg;
            const float hn = ov * ftanh(c_reg);
            hn_prev = hn;
            cn_prev = c_reg;

            __nv_bfloat16 hh = __float2bfloat16(hn);
            __nv_bfloat16 hl = __float2bfloat16(hn - __bfloat162float(hh));
            hhi[ooff] = hh;
            hlo[ooff] = hl;

            // prefetch Xg for next step (latency hides in the barrier)
            if (s + 1 < SS)
                xv = *(const float4*)(xsrc + (size_t)(s + 1) * BB * G4H);
        }

        // ---- grid barrier (writer-only fence; R11-proven tid0 spin) ----
        if (tid < 256) __threadfence();
        __syncthreads();
        if (tid == 0) {
            const unsigned target = (s & 1) ? 0u : 1u;
            unsigned old = atomicAdd(&g_bar_ctr, 1u);
            if (old == GRID - 1) {
                atomicExch(&g_bar_ctr, 0u);
                __threadfence();
                g_bar_flag = target;
            } else {
                while (g_bar_flag != target) { }
            }
            __threadfence();
        }
        __syncthreads();
    }

    // ---- final deferred stores + final state ----
    if (tid < 256) {
        const size_t po = (size_t)(SS - 1) * BH + ooff;
        all_h1[po] = hn_prev;
        all_h2[po] = hn_prev;
        all_c [po] = cn_prev;
        h_f[ooff] = hn_prev;
        c_f[ooff] = cn_prev;
    }
}

// ============================================================================
// Launch
// ============================================================================
extern "C" void kernel_launch(void* const* d_in, const int* in_sizes, int n_in,
                              void* d_out, int out_size)
{
    const float* layer_input = (const float*)d_in[0];  // [S,B,D]
    const float* h_t         = (const float*)d_in[1];  // [B,H]
    const float* c_t         = (const float*)d_in[2];  // [B,H]
    const float* U           = (const float*)d_in[3];  // [4H,D]
    const float* V           = (const float*)d_in[4];  // [4H,H]
    const float* bih         = (const float*)d_in[5];  // [4H]
    const float* bhh         = (const float*)d_in[6];  // [4H]

    float* out = (float*)d_out;
    float* all_h1 = out;
    float* h_f    = out + (size_t)SS * BH;
    float* c_f    = h_f + BH;
    float* all_h2 = c_f + BH;
    float* all_c  = all_h2 + (size_t)SS * BH;

    float* Xp = nullptr;
    cudaGetSymbolAddress((void**)&Xp, g_X);
    __nv_bfloat16 *Ahi, *Alo, *Uhi, *Ulo, *Vhi, *Vlo, *hhi, *hlo;
    cudaGetSymbolAddress((void**)&Ahi, g_Ahi);
    cudaGetSymbolAddress((void**)&Alo, g_Alo);
    cudaGetSymbolAddress((void**)&Uhi, g_Uhi);
    cudaGetSymbolAddress((void**)&Ulo, g_Ulo);
    cudaGetSymbolAddress((void**)&Vhi, g_Vhi);
    cudaGetSymbolAddress((void**)&Vlo, g_Vlo);
    cudaGetSymbolAddress((void**)&hhi, g_hhi);
    cudaGetSymbolAddress((void**)&hlo, g_hlo);

    cudaFuncSetAttribute(lstm_persistent,
                         cudaFuncAttributeMaxDynamicSharedMemorySize, PERS_SMEM);
    cudaFuncSetAttribute(gemm_x_hmma,
                         cudaFuncAttributeMaxDynamicSharedMemorySize, GEMM_SMEM);

    // 0) fused bf16 hi/lo splits: A, U, V, h0 in one launch
    split_bf16_all<<<(N4_TOTAL + 255) / 256, 256>>>(layer_input, U, V, h_t);

    // 1) HMMA input projection + bias (2-stage cp.async, 2 CTAs/SM)
    dim3 gg(G4H / 128, (SS * BB) / 128);   // (32, 128)
    gemm_x_hmma<<<gg, 256, GEMM_SMEM>>>(Ahi, Alo, Uhi, Ulo, bih, bhh, Xp);

    // 2) persistent HMMA recurrence (all 512 steps)
    lstm_persistent<<<GRID, PTHREADS, PERS_SMEM>>>(
        Xp, c_t, Vhi, Vlo, hhi, hlo,
        all_h1, all_h2, all_c, h_f, c_f);
}